// round 13
// baseline (speedup 1.0000x reference)
#include <cuda_runtime.h>
#include <cuda_bf16.h>
#include <cstdint>

#define NV 4096
#define NE 8192
#define FV 128
#define FE 64
#define FOUT 128

// Scratch (allocation-free rule: __device__ globals)
__device__ float g_d[NE];
__device__ float g_HW[NV * FOUT];
__device__ float g_M[(size_t)NV * NV];
// bf16 split copies of T: A = T*d (col k scaled by d[k]), B = T
__device__ __nv_bfloat16 g_Ah[(size_t)NV * NE];
__device__ __nv_bfloat16 g_Al[(size_t)NV * NE];
__device__ __nv_bfloat16 g_Bh[(size_t)NV * NE];
__device__ __nv_bfloat16 g_Bl[(size_t)NV * NE];

// ======================= helpers =======================
__device__ __forceinline__ uint32_t smem_u32(const void* p) {
    uint32_t a;
    asm("{ .reg .u64 t; cvta.to.shared.u64 t, %1; cvt.u32.u64 %0, t; }" : "=r"(a) : "l"(p));
    return a;
}
__device__ __forceinline__ void split2(float x, float y, uint32_t& hi, uint32_t& lo) {
    __nv_bfloat162 h = __floats2bfloat162_rn(x, y);
    uint32_t hb = *(uint32_t*)&h;
    float hx = __uint_as_float(hb << 16);
    float hy = __uint_as_float(hb & 0xFFFF0000u);
    __nv_bfloat162 l = __floats2bfloat162_rn(x - hx, y - hy);
    hi = hb;
    lo = *(uint32_t*)&l;
}
__device__ __forceinline__ void mma16816(float* c, const uint32_t* a, const uint32_t* b) {
    asm volatile(
        "mma.sync.aligned.m16n8k16.row.col.f32.bf16.bf16.f32 "
        "{%0,%1,%2,%3}, {%4,%5,%6,%7}, {%8,%9}, {%0,%1,%2,%3};"
        : "+f"(c[0]), "+f"(c[1]), "+f"(c[2]), "+f"(c[3])
        : "r"(a[0]), "r"(a[1]), "r"(a[2]), "r"(a[3]), "r"(b[0]), "r"(b[1]));
}
__device__ __forceinline__ void ldsm_x4(uint32_t* r, uint32_t addr) {
    asm volatile("ldmatrix.sync.aligned.m8n8.x4.shared.b16 {%0,%1,%2,%3}, [%4];"
                 : "=r"(r[0]), "=r"(r[1]), "=r"(r[2]), "=r"(r[3]) : "r"(addr));
}
__device__ __forceinline__ void cp16cg(uint32_t saddr, const void* gaddr) {
    asm volatile("cp.async.cg.shared.global [%0], [%1], 16;" :: "r"(saddr), "l"(gaddr));
}

// ---------------- kernel 1: d[e] = dot(H_e[e,:], p) ----------------
__global__ void k_edge_dot(const float* __restrict__ He, const float* __restrict__ p) {
    int row  = blockIdx.x * 8 + (threadIdx.x >> 5);
    int lane = threadIdx.x & 31;
    const float* r = He + (size_t)row * FE;
    float s = r[lane] * p[lane] + r[lane + 32] * p[lane + 32];
    #pragma unroll
    for (int o = 16; o; o >>= 1) s += __shfl_xor_sync(0xffffffffu, s, o);
    if (lane == 0) g_d[row] = s;
}

// ---------------- kernel 1b: bf16 split precompute ----------------
__global__ void __launch_bounds__(256) k_split(const float* __restrict__ T) {
    size_t idx = (size_t)blockIdx.x * 256 + threadIdx.x;
    int row = (int)(idx >> 10);
    int c0  = (int)(idx & 1023) * 8;
    const float* pt = T + (size_t)row * NE + c0;
    float4 t0 = *(const float4*)pt;
    float4 t1 = *(const float4*)(pt + 4);
    float4 d0 = *(const float4*)(g_d + c0);
    float4 d1 = *(const float4*)(g_d + c0 + 4);

    uint4 bh, bl, ah, al;
    split2(t0.x, t0.y, bh.x, bl.x);
    split2(t0.z, t0.w, bh.y, bl.y);
    split2(t1.x, t1.y, bh.z, bl.z);
    split2(t1.z, t1.w, bh.w, bl.w);
    split2(t0.x * d0.x, t0.y * d0.y, ah.x, al.x);
    split2(t0.z * d0.z, t0.w * d0.w, ah.y, al.y);
    split2(t1.x * d1.x, t1.y * d1.y, ah.z, al.z);
    split2(t1.z * d1.z, t1.w * d1.w, ah.w, al.w);

    size_t boff = ((size_t)row * NE + c0) * 2;
    *(uint4*)((char*)g_Ah + boff) = ah;
    *(uint4*)((char*)g_Al + boff) = al;
    *(uint4*)((char*)g_Bh + boff) = bh;
    *(uint4*)((char*)g_Bl + boff) = bl;
}

// ---------------- kernel 2: HW = H_v @ W  (16 rows / block) ----------------
__global__ void k_hw(const float* __restrict__ Hv, const float* __restrict__ W) {
    __shared__ float sh[16][FV];
    int r0  = blockIdx.x * 16;
    int tid = threadIdx.x;
    #pragma unroll
    for (int l = 0; l < 4; l++) {
        int idx = tid + l * 128;
        int r = idx >> 5;
        int c = (idx & 31) * 4;
        *(float4*)&sh[r][c] = *(const float4*)&Hv[(size_t)(r0 + r) * FV + c];
    }
    __syncthreads();
    int c = tid;
    float acc[16];
    #pragma unroll
    for (int r = 0; r < 16; r++) acc[r] = 0.f;
    for (int k = 0; k < FV; k++) {
        float w = W[k * FOUT + c];
        #pragma unroll
        for (int r = 0; r < 16; r++) acc[r] += sh[r][k] * w;
    }
    #pragma unroll
    for (int r = 0; r < 16; r++) g_HW[(size_t)(r0 + r) * FOUT + c] = acc[r];
}

// ---------------- kernel 3: M = (T*d) @ T^T via mma.sync bf16x3 ------------
// R7 build + one change: cp.async issue moved to right after the B-fragment
// LDSMs (stage (s+2)%3 was last read in iter s-1; this iteration's barrier
// already ordered those reads -> WAR-safe). DMA starts ~1600cyc earlier/chunk.
// byte(row, c16) = row*32 + ((c16 ^ ((row>>2)&1)) * 16)   -- conflict-free.
#define STG_B 16384
#define A_AH 0
#define A_AL 4096
#define A_BH 8192
#define A_BL 12288

__global__ void __launch_bounds__(256, 2) k_mult_hmma() {
    // triangular decode: blockIdx.x in [0, 528)
    int idx = blockIdx.x;
    int bi = (int)((sqrtf(8.0f * (float)idx + 1.0f) - 1.0f) * 0.5f);
    while ((bi + 1) * (bi + 2) / 2 <= idx) bi++;
    while (bi * (bi + 1) / 2 > idx) bi--;
    int bj = idx - bi * (bi + 1) / 2;

    __shared__ __align__(128) char smem[3 * STG_B];
    const uint32_t sb = smem_u32(smem);

    const int tid = threadIdx.x, lane = tid & 31, wid = tid >> 5;
    const int wr = wid >> 2, wc = wid & 3;

    float acc[4][4][4];
    #pragma unroll
    for (int i = 0; i < 4; i++)
        #pragma unroll
        for (int j = 0; j < 4; j++)
            #pragma unroll
            for (int q = 0; q < 4; q++) acc[i][j][q] = 0.f;

    // cp.async mapping: thread -> (row = tid>>1, c16 = tid&1), one 16B per array.
    const int crow = tid >> 1;
    const int cc   = tid & 1;
    const uint32_t cdst = (uint32_t)(crow * 32 + ((cc ^ ((crow >> 2) & 1)) * 16));
    const __nv_bfloat16* gAh_t = g_Ah + (size_t)(bi * 128 + crow) * NE + cc * 8;
    const __nv_bfloat16* gAl_t = g_Al + (size_t)(bi * 128 + crow) * NE + cc * 8;
    const __nv_bfloat16* gBh_t = g_Bh + (size_t)(bj * 128 + crow) * NE + cc * 8;
    const __nv_bfloat16* gBl_t = g_Bl + (size_t)(bj * 128 + crow) * NE + cc * 8;

    #define ISSUE(stage, k0)                                   \
        do {                                                   \
            uint32_t st_ = sb + (stage) * STG_B;               \
            cp16cg(st_ + A_AH + cdst, gAh_t + (k0));           \
            cp16cg(st_ + A_AL + cdst, gAl_t + (k0));           \
            cp16cg(st_ + A_BH + cdst, gBh_t + (k0));           \
            cp16cg(st_ + A_BL + cdst, gBl_t + (k0));           \
        } while (0)

    // ldmatrix lane bases
    const int arow_l = wr * 64 + (lane & 15);               // + mt*16
    const int ac     = lane >> 4;                           // k-half of chunk
    const int bm     = lane >> 3;
    const int brow_l = wc * 32 + (bm >> 1) * 8 + (lane & 7); // + np*16
    const int bc     = bm & 1;

    // prologue: 2 stages in flight
    ISSUE(0, 0);
    asm volatile("cp.async.commit_group;");
    ISSUE(1, 16);
    asm volatile("cp.async.commit_group;");

    const int NCHUNK = NE / 16;   // 512
    int cstg = 0;                 // compute stage = s % 3
    int istg = 2;                 // issue stage   = (s+2) % 3
    for (int s = 0; s < NCHUNK; s++) {
        asm volatile("cp.async.wait_group 1;" ::: "memory");
        __syncthreads();

        const uint32_t st = sb + cstg * STG_B;
        uint32_t bh[2][4], bl[2][4];   // [n16-pair][4 regs = 2 n8 tiles]
        #pragma unroll
        for (int np = 0; np < 2; np++) {
            int row = brow_l + np * 16;
            uint32_t off = (uint32_t)(row * 32 + ((bc ^ ((row >> 2) & 1)) * 16));
            ldsm_x4(bh[np], st + A_BH + off);
            ldsm_x4(bl[np], st + A_BL + off);
        }

        // issue chunk s+2 now: DMA overlaps this chunk's MMA work.
        int k2 = (s + 2) * 16;
        if (k2 < NE) ISSUE(istg, k2);
        asm volatile("cp.async.commit_group;");

        #pragma unroll
        for (int mt = 0; mt < 4; mt++) {
            int row = arow_l + mt * 16;
            uint32_t off = (uint32_t)(row * 32 + ((ac ^ ((row >> 2) & 1)) * 16));
            uint32_t ah[4], al[4];
            ldsm_x4(ah, st + A_AH + off);
            ldsm_x4(al, st + A_AL + off);
            #pragma unroll
            for (int nt = 0; nt < 4; nt++) {
                const uint32_t* pbh = &bh[nt >> 1][(nt & 1) * 2];
                const uint32_t* pbl = &bl[nt >> 1][(nt & 1) * 2];
                mma16816(acc[mt][nt], ah, pbh);
                mma16816(acc[mt][nt], ah, pbl);
                mma16816(acc[mt][nt], al, pbh);
            }
        }

        if (++cstg == 3) cstg = 0;
        if (++istg == 3) istg = 0;
    }

    // ---- writeback: primary (+ mirror when off-diagonal) ----
    const int g  = lane >> 2;
    const int cp = (lane & 3) * 2;
    #pragma unroll
    for (int mt = 0; mt < 4; mt++)
        #pragma unroll
        for (int nt = 0; nt < 4; nt++) {
            float* c = acc[mt][nt];
            int r = bi * 128 + wr * 64 + mt * 16 + g;
            int q = bj * 128 + wc * 32 + nt * 8 + cp;
            *(float2*)&g_M[(size_t)r * NV + q]       = make_float2(c[0], c[1]);
            *(float2*)&g_M[(size_t)(r + 8) * NV + q] = make_float2(c[2], c[3]);
            if (bi != bj) {
                g_M[(size_t)q * NV + r]           = c[0];
                g_M[(size_t)(q + 1) * NV + r]     = c[1];
                g_M[(size_t)q * NV + r + 8]       = c[2];
                g_M[(size_t)(q + 1) * NV + r + 8] = c[3];
            }
        }
}

// ---------------- kernel 4: out = (mask(M) * adj_v) @ HW + bias -------------
// 256 CTAs x 16 rows, k-chunk 16, 3-stage cp.async (R7 skeleton), 30KB static.
__global__ void __launch_bounds__(256) k_out(const float* __restrict__ adj_v,
                                             const float* __restrict__ bias,
                                             float* __restrict__ out) {
    __shared__ float sAdj[3][16][16];   // [stage][row][k]
    __shared__ float sM[3][16][16];
    __shared__ float sB[3][16][128];    // [stage][k][col]

    const int bi  = blockIdx.x;
    const int tid = threadIdx.x;
    const int tx  = tid & 31;           // col group (*4)
    const int ty  = tid >> 5;           // row group (*2)

    const uint32_t uAdj = smem_u32(sAdj);
    const uint32_t uM   = smem_u32(sM);
    const uint32_t uB   = smem_u32(sB);

    float acc[2][4];
    #pragma unroll
    for (int i = 0; i < 2; i++)
        #pragma unroll
        for (int j = 0; j < 4; j++) acc[i][j] = 0.f;

    const int at  = tid & 63;
    const int ar  = at >> 2, ac4 = (at & 3) * 4;
    const size_t arow_base = (size_t)(bi * 16 + ar) * NV + ac4;

    #define ISSUE_O(stage, j0)                                                   \
        do {                                                                     \
            if (tid < 64)                                                        \
                cp16cg(uAdj + (stage) * 1024 + at * 16, adj_v + arow_base + (j0)); \
            else if (tid < 128)                                                  \
                cp16cg(uM + (stage) * 1024 + at * 16, g_M + arow_base + (j0));   \
            _Pragma("unroll")                                                    \
            for (int l = 0; l < 2; l++) {                                        \
                int bidx = tid + l * 256;                                        \
                cp16cg(uB + (stage) * 8192 + bidx * 16,                          \
                       g_HW + (size_t)((j0) + (bidx >> 5)) * FOUT + (bidx & 31) * 4); \
            }                                                                    \
        } while (0)

    ISSUE_O(0, 0);
    asm volatile("cp.async.commit_group;");
    ISSUE_O(1, 16);
    asm volatile("cp.async.commit_group;");

    const int gi0 = bi * 16 + ty * 2;
    const int NCH = NV / 16;   // 256
    int cstg = 0, istg = 2;
    for (int s = 0; s < NCH; s++) {
        asm volatile("cp.async.wait_group 1;" ::: "memory");
        __syncthreads();

        const int j0 = s * 16;
        #pragma unroll
        for (int kk = 0; kk < 16; kk++) {
            float4 b = *(const float4*)&sB[cstg][kk][tx * 4];
            #pragma unroll
            for (int i = 0; i < 2; i++) {
                float adjv = sAdj[cstg][ty * 2 + i][kk];
                float mv   = sM[cstg][ty * 2 + i][kk];
                float a = (gi0 + i == j0 + kk) ? adjv : adjv * mv;
                acc[i][0] += a * b.x;
                acc[i][1] += a * b.y;
                acc[i][2] += a * b.z;
                acc[i][3] += a * b.w;
            }
        }

        int k2 = (s + 2) * 16;
        if (k2 < NV) ISSUE_O(istg, k2);
        asm volatile("cp.async.commit_group;");
        if (++cstg == 3) cstg = 0;
        if (++istg == 3) istg = 0;
    }

    float4 bv = *(const float4*)&bias[tx * 4];
    #pragma unroll
    for (int i = 0; i < 2; i++) {
        size_t gi = (size_t)(bi * 16 + ty * 2 + i);
        float4 v = make_float4(acc[i][0] + bv.x, acc[i][1] + bv.y,
                               acc[i][2] + bv.z, acc[i][3] + bv.w);
        *(float4*)&out[gi * FOUT + tx * 4] = v;
    }
}

// ---------------- launch ----------------
extern "C" void kernel_launch(void* const* d_in, const int* in_sizes, int n_in,
                              void* d_out, int out_size) {
    const float* Hv    = (const float*)d_in[0];
    const float* He    = (const float*)d_in[1];
    // d_in[2] = adj_e: unused by the node_layer path
    const float* adj_v = (const float*)d_in[3];
    const float* T     = (const float*)d_in[4];
    const float* W     = (const float*)d_in[5];
    const float* p     = (const float*)d_in[6];
    const float* bias  = (const float*)d_in[7];
    float* out = (float*)d_out;

    k_edge_dot<<<NE / 8, 256>>>(He, p);
    k_split<<<(NV * (NE / 8)) / 256, 256>>>(T);
    k_hw<<<NV / 16, 128>>>(Hv, W);
    k_mult_hmma<<<528, 256>>>();
    k_out<<<NV / 16, 256>>>(adj_v, bias, out);

    // second output of the tuple: H_e passthrough
    if (out_size >= NV * FOUT + NE * FE) {
        cudaMemcpyAsync(out + NV * FOUT, He, (size_t)NE * FE * sizeof(float),
                        cudaMemcpyDeviceToDevice);
    }
}

// round 14
// speedup vs baseline: 1.1524x; 1.1524x over previous
#include <cuda_runtime.h>
#include <cuda_bf16.h>
#include <cstdint>

#define NV 4096
#define NE 8192
#define FV 128
#define FE 64
#define FOUT 128

// Scratch (allocation-free rule: __device__ globals)
__device__ float g_d[NE];
__device__ float g_HW[NV * FOUT];
__device__ float g_M[(size_t)NV * NV];
// bf16 split copies of T: A = T*d (col k scaled by d[k]), B = T
__device__ __nv_bfloat16 g_Ah[(size_t)NV * NE];
__device__ __nv_bfloat16 g_Al[(size_t)NV * NE];
__device__ __nv_bfloat16 g_Bh[(size_t)NV * NE];
__device__ __nv_bfloat16 g_Bl[(size_t)NV * NE];

// ======================= helpers =======================
__device__ __forceinline__ uint32_t smem_u32(const void* p) {
    uint32_t a;
    asm("{ .reg .u64 t; cvta.to.shared.u64 t, %1; cvt.u32.u64 %0, t; }" : "=r"(a) : "l"(p));
    return a;
}
__device__ __forceinline__ void split2(float x, float y, uint32_t& hi, uint32_t& lo) {
    __nv_bfloat162 h = __floats2bfloat162_rn(x, y);
    uint32_t hb = *(uint32_t*)&h;
    float hx = __uint_as_float(hb << 16);
    float hy = __uint_as_float(hb & 0xFFFF0000u);
    __nv_bfloat162 l = __floats2bfloat162_rn(x - hx, y - hy);
    hi = hb;
    lo = *(uint32_t*)&l;
}
__device__ __forceinline__ void mma16816(float* c, const uint32_t* a, const uint32_t* b) {
    asm volatile(
        "mma.sync.aligned.m16n8k16.row.col.f32.bf16.bf16.f32 "
        "{%0,%1,%2,%3}, {%4,%5,%6,%7}, {%8,%9}, {%0,%1,%2,%3};"
        : "+f"(c[0]), "+f"(c[1]), "+f"(c[2]), "+f"(c[3])
        : "r"(a[0]), "r"(a[1]), "r"(a[2]), "r"(a[3]), "r"(b[0]), "r"(b[1]));
}
__device__ __forceinline__ void ldsm_x4(uint32_t* r, uint32_t addr) {
    asm volatile("ldmatrix.sync.aligned.m8n8.x4.shared.b16 {%0,%1,%2,%3}, [%4];"
                 : "=r"(r[0]), "=r"(r[1]), "=r"(r[2]), "=r"(r[3]) : "r"(addr));
}
__device__ __forceinline__ void cp16cg(uint32_t saddr, const void* gaddr) {
    asm volatile("cp.async.cg.shared.global [%0], [%1], 16;" :: "r"(saddr), "l"(gaddr));
}

// ---------------- kernel 1: d[e] = dot(H_e[e,:], p) ----------------
__global__ void k_edge_dot(const float* __restrict__ He, const float* __restrict__ p) {
    int row  = blockIdx.x * 8 + (threadIdx.x >> 5);
    int lane = threadIdx.x & 31;
    const float* r = He + (size_t)row * FE;
    float s = r[lane] * p[lane] + r[lane + 32] * p[lane + 32];
    #pragma unroll
    for (int o = 16; o; o >>= 1) s += __shfl_xor_sync(0xffffffffu, s, o);
    if (lane == 0) g_d[row] = s;
}

// ---------------- kernel 1b: bf16 split precompute ----------------
__global__ void __launch_bounds__(256) k_split(const float* __restrict__ T) {
    size_t idx = (size_t)blockIdx.x * 256 + threadIdx.x;
    int row = (int)(idx >> 10);
    int c0  = (int)(idx & 1023) * 8;
    const float* pt = T + (size_t)row * NE + c0;
    float4 t0 = *(const float4*)pt;
    float4 t1 = *(const float4*)(pt + 4);
    float4 d0 = *(const float4*)(g_d + c0);
    float4 d1 = *(const float4*)(g_d + c0 + 4);

    uint4 bh, bl, ah, al;
    split2(t0.x, t0.y, bh.x, bl.x);
    split2(t0.z, t0.w, bh.y, bl.y);
    split2(t1.x, t1.y, bh.z, bl.z);
    split2(t1.z, t1.w, bh.w, bl.w);
    split2(t0.x * d0.x, t0.y * d0.y, ah.x, al.x);
    split2(t0.z * d0.z, t0.w * d0.w, ah.y, al.y);
    split2(t1.x * d1.x, t1.y * d1.y, ah.z, al.z);
    split2(t1.z * d1.z, t1.w * d1.w, ah.w, al.w);

    size_t boff = ((size_t)row * NE + c0) * 2;
    *(uint4*)((char*)g_Ah + boff) = ah;
    *(uint4*)((char*)g_Al + boff) = al;
    *(uint4*)((char*)g_Bh + boff) = bh;
    *(uint4*)((char*)g_Bl + boff) = bl;
}

// ---------------- kernel 2: HW = H_v @ W  (16 rows / block) ----------------
__global__ void k_hw(const float* __restrict__ Hv, const float* __restrict__ W) {
    __shared__ float sh[16][FV];
    int r0  = blockIdx.x * 16;
    int tid = threadIdx.x;
    #pragma unroll
    for (int l = 0; l < 4; l++) {
        int idx = tid + l * 128;
        int r = idx >> 5;
        int c = (idx & 31) * 4;
        *(float4*)&sh[r][c] = *(const float4*)&Hv[(size_t)(r0 + r) * FV + c];
    }
    __syncthreads();
    int c = tid;
    float acc[16];
    #pragma unroll
    for (int r = 0; r < 16; r++) acc[r] = 0.f;
    for (int k = 0; k < FV; k++) {
        float w = W[k * FOUT + c];
        #pragma unroll
        for (int r = 0; r < 16; r++) acc[r] += sh[r][k] * w;
    }
    #pragma unroll
    for (int r = 0; r < 16; r++) g_HW[(size_t)(r0 + r) * FOUT + c] = acc[r];
}

// ---------------- kernel 3: M = (T*d) @ T^T via mma.sync bf16x3 ------------
// R11 build (proven 1040us) with the mainloop unrolled x3 so every stage index
// is a compile-time constant: all LDSM/LDGSTS smem addresses become
// loop-invariant, shortening the post-barrier restart. Chunk ordering,
// wait_group accounting, and issue-after-compute placement are unchanged.
// byte(row, c16) = row*32 + ((c16 ^ ((row>>2)&1)) * 16)   -- conflict-free.
#define STG_B 16384
#define A_AH 0
#define A_AL 4096
#define A_BH 8192
#define A_BL 12288

__global__ void __launch_bounds__(256, 2) k_mult_hmma() {
    // triangular decode: blockIdx.x in [0, 528)
    int idx = blockIdx.x;
    int bi = (int)((sqrtf(8.0f * (float)idx + 1.0f) - 1.0f) * 0.5f);
    while ((bi + 1) * (bi + 2) / 2 <= idx) bi++;
    while (bi * (bi + 1) / 2 > idx) bi--;
    int bj = idx - bi * (bi + 1) / 2;

    __shared__ __align__(128) char smem[3 * STG_B];
    const uint32_t sb = smem_u32(smem);

    const int tid = threadIdx.x, lane = tid & 31, wid = tid >> 5;
    const int wr = wid >> 2, wc = wid & 3;

    float acc[4][4][4];
    #pragma unroll
    for (int i = 0; i < 4; i++)
        #pragma unroll
        for (int j = 0; j < 4; j++)
            #pragma unroll
            for (int q = 0; q < 4; q++) acc[i][j][q] = 0.f;

    // cp.async mapping: thread -> (row = tid>>1, c16 = tid&1), one 16B per array.
    const int crow = tid >> 1;
    const int cc   = tid & 1;
    const uint32_t cdst = (uint32_t)(crow * 32 + ((cc ^ ((crow >> 2) & 1)) * 16));
    const __nv_bfloat16* gAh_t = g_Ah + (size_t)(bi * 128 + crow) * NE + cc * 8;
    const __nv_bfloat16* gAl_t = g_Al + (size_t)(bi * 128 + crow) * NE + cc * 8;
    const __nv_bfloat16* gBh_t = g_Bh + (size_t)(bj * 128 + crow) * NE + cc * 8;
    const __nv_bfloat16* gBl_t = g_Bl + (size_t)(bj * 128 + crow) * NE + cc * 8;

    #define ISSUE(stage, k0)                                   \
        do {                                                   \
            uint32_t st_ = sb + (stage) * STG_B;               \
            cp16cg(st_ + A_AH + cdst, gAh_t + (k0));           \
            cp16cg(st_ + A_AL + cdst, gAl_t + (k0));           \
            cp16cg(st_ + A_BH + cdst, gBh_t + (k0));           \
            cp16cg(st_ + A_BL + cdst, gBl_t + (k0));           \
        } while (0)

    // ldmatrix lane bases (loop-invariant offsets within a stage)
    const int arow_l = wr * 64 + (lane & 15);               // + mt*16
    const int ac     = lane >> 4;                           // k-half of chunk
    const int bm     = lane >> 3;
    const int brow_l = wc * 32 + (bm >> 1) * 8 + (lane & 7); // + np*16
    const int bc     = bm & 1;

    uint32_t offB[2], offA[4];
    #pragma unroll
    for (int np = 0; np < 2; np++) {
        int row = brow_l + np * 16;
        offB[np] = (uint32_t)(row * 32 + ((bc ^ ((row >> 2) & 1)) * 16));
    }
    #pragma unroll
    for (int mt = 0; mt < 4; mt++) {
        int row = arow_l + mt * 16;
        offA[mt] = (uint32_t)(row * 32 + ((ac ^ ((row >> 2) & 1)) * 16));
    }

    // One chunk: wait, sync, compute from compile-time stage CSTG, then issue
    // the chunk 2 ahead into compile-time stage ISTG (R11 ordering).
    #define CHUNK(CSTG, ISTG)                                                  \
        do {                                                                   \
            asm volatile("cp.async.wait_group 1;" ::: "memory");               \
            __syncthreads();                                                   \
            const uint32_t st = sb + (CSTG) * STG_B;                           \
            uint32_t bh[2][4], bl[2][4];                                       \
            _Pragma("unroll")                                                  \
            for (int np = 0; np < 2; np++) {                                   \
                ldsm_x4(bh[np], st + A_BH + offB[np]);                         \
                ldsm_x4(bl[np], st + A_BL + offB[np]);                         \
            }                                                                  \
            _Pragma("unroll")                                                  \
            for (int mt = 0; mt < 4; mt++) {                                   \
                uint32_t ah[4], al[4];                                         \
                ldsm_x4(ah, st + A_AH + offA[mt]);                             \
                ldsm_x4(al, st + A_AL + offA[mt]);                             \
                _Pragma("unroll")                                              \
                for (int nt = 0; nt < 4; nt++) {                               \
                    const uint32_t* pbh = &bh[nt >> 1][(nt & 1) * 2];          \
                    const uint32_t* pbl = &bl[nt >> 1][(nt & 1) * 2];          \
                    mma16816(acc[mt][nt], ah, pbh);                            \
                    mma16816(acc[mt][nt], ah, pbl);                            \
                    mma16816(acc[mt][nt], al, pbh);                            \
                }                                                              \
            }                                                                  \
            if (k_next < NE) ISSUE(ISTG, k_next);                              \
            asm volatile("cp.async.commit_group;");                            \
            k_next += 16;                                                      \
        } while (0)

    // prologue: 2 stages in flight
    ISSUE(0, 0);
    asm volatile("cp.async.commit_group;");
    ISSUE(1, 16);
    asm volatile("cp.async.commit_group;");

    int k_next = 32;   // k of chunk s+2
    // 512 chunks = 170 * 3 + 2
    #pragma unroll 1
    for (int s3 = 0; s3 < 170; s3++) {
        CHUNK(0, 2);
        CHUNK(1, 0);
        CHUNK(2, 1);
    }
    CHUNK(0, 2);   // s = 510 (k_next >= NE, no issue)
    CHUNK(1, 0);   // s = 511

    // ---- writeback: primary (+ mirror when off-diagonal) ----
    const int g  = lane >> 2;
    const int cp = (lane & 3) * 2;
    #pragma unroll
    for (int mt = 0; mt < 4; mt++)
        #pragma unroll
        for (int nt = 0; nt < 4; nt++) {
            float* c = acc[mt][nt];
            int r = bi * 128 + wr * 64 + mt * 16 + g;
            int q = bj * 128 + wc * 32 + nt * 8 + cp;
            *(float2*)&g_M[(size_t)r * NV + q]       = make_float2(c[0], c[1]);
            *(float2*)&g_M[(size_t)(r + 8) * NV + q] = make_float2(c[2], c[3]);
            if (bi != bj) {
                g_M[(size_t)q * NV + r]           = c[0];
                g_M[(size_t)(q + 1) * NV + r]     = c[1];
                g_M[(size_t)q * NV + r + 8]       = c[2];
                g_M[(size_t)(q + 1) * NV + r + 8] = c[3];
            }
        }
}

// ---------------- kernel 4: out = (mask(M) * adj_v) @ HW + bias -------------
// 256 CTAs x 16 rows, k-chunk 16, 3-stage cp.async (R7 skeleton), 30KB static.
__global__ void __launch_bounds__(256) k_out(const float* __restrict__ adj_v,
                                             const float* __restrict__ bias,
                                             float* __restrict__ out) {
    __shared__ float sAdj[3][16][16];   // [stage][row][k]
    __shared__ float sM[3][16][16];
    __shared__ float sB[3][16][128];    // [stage][k][col]

    const int bi  = blockIdx.x;
    const int tid = threadIdx.x;
    const int tx  = tid & 31;           // col group (*4)
    const int ty  = tid >> 5;           // row group (*2)

    const uint32_t uAdj = smem_u32(sAdj);
    const uint32_t uM   = smem_u32(sM);
    const uint32_t uB   = smem_u32(sB);

    float acc[2][4];
    #pragma unroll
    for (int i = 0; i < 2; i++)
        #pragma unroll
        for (int j = 0; j < 4; j++) acc[i][j] = 0.f;

    const int at  = tid & 63;
    const int ar  = at >> 2, ac4 = (at & 3) * 4;
    const size_t arow_base = (size_t)(bi * 16 + ar) * NV + ac4;

    #define ISSUE_O(stage, j0)                                                   \
        do {                                                                     \
            if (tid < 64)                                                        \
                cp16cg(uAdj + (stage) * 1024 + at * 16, adj_v + arow_base + (j0)); \
            else if (tid < 128)                                                  \
                cp16cg(uM + (stage) * 1024 + at * 16, g_M + arow_base + (j0));   \
            _Pragma("unroll")                                                    \
            for (int l = 0; l < 2; l++) {                                        \
                int bidx = tid + l * 256;                                        \
                cp16cg(uB + (stage) * 8192 + bidx * 16,                          \
                       g_HW + (size_t)((j0) + (bidx >> 5)) * FOUT + (bidx & 31) * 4); \
            }                                                                    \
        } while (0)

    ISSUE_O(0, 0);
    asm volatile("cp.async.commit_group;");
    ISSUE_O(1, 16);
    asm volatile("cp.async.commit_group;");

    const int gi0 = bi * 16 + ty * 2;
    const int NCH = NV / 16;   // 256
    int cstg = 0, istg = 2;
    for (int s = 0; s < NCH; s++) {
        asm volatile("cp.async.wait_group 1;" ::: "memory");
        __syncthreads();

        const int j0 = s * 16;
        #pragma unroll
        for (int kk = 0; kk < 16; kk++) {
            float4 b = *(const float4*)&sB[cstg][kk][tx * 4];
            #pragma unroll
            for (int i = 0; i < 2; i++) {
                float adjv = sAdj[cstg][ty * 2 + i][kk];
                float mv   = sM[cstg][ty * 2 + i][kk];
                float a = (gi0 + i == j0 + kk) ? adjv : adjv * mv;
                acc[i][0] += a * b.x;
                acc[i][1] += a * b.y;
                acc[i][2] += a * b.z;
                acc[i][3] += a * b.w;
            }
        }

        int k2 = (s + 2) * 16;
        if (k2 < NV) ISSUE_O(istg, k2);
        asm volatile("cp.async.commit_group;");
        if (++cstg == 3) cstg = 0;
        if (++istg == 3) istg = 0;
    }

    float4 bv = *(const float4*)&bias[tx * 4];
    #pragma unroll
    for (int i = 0; i < 2; i++) {
        size_t gi = (size_t)(bi * 16 + ty * 2 + i);
        float4 v = make_float4(acc[i][0] + bv.x, acc[i][1] + bv.y,
                               acc[i][2] + bv.z, acc[i][3] + bv.w);
        *(float4*)&out[gi * FOUT + tx * 4] = v;
    }
}

// ---------------- launch ----------------
extern "C" void kernel_launch(void* const* d_in, const int* in_sizes, int n_in,
                              void* d_out, int out_size) {
    const float* Hv    = (const float*)d_in[0];
    const float* He    = (const float*)d_in[1];
    // d_in[2] = adj_e: unused by the node_layer path
    const float* adj_v = (const float*)d_in[3];
    const float* T     = (const float*)d_in[4];
    const float* W     = (const float*)d_in[5];
    const float* p     = (const float*)d_in[6];
    const float* bias  = (const float*)d_in[7];
    float* out = (float*)d_out;

    k_edge_dot<<<NE / 8, 256>>>(He, p);
    k_split<<<(NV * (NE / 8)) / 256, 256>>>(T);
    k_hw<<<NV / 16, 128>>>(Hv, W);
    k_mult_hmma<<<528, 256>>>();
    k_out<<<NV / 16, 256>>>(adj_v, bias, out);

    // second output of the tuple: H_e passthrough
    if (out_size >= NV * FOUT + NE * FE) {
        cudaMemcpyAsync(out + NV * FOUT, He, (size_t)NE * FE * sizeof(float),
                        cudaMemcpyDeviceToDevice);
    }
}

// round 15
// speedup vs baseline: 1.2387x; 1.0749x over previous
#include <cuda_runtime.h>
#include <cuda_bf16.h>
#include <cstdint>

#define NV 4096
#define NE 8192
#define FV 128
#define FE 64
#define FOUT 128

// Scratch (allocation-free rule: __device__ globals)
__device__ float g_d[NE];
__device__ float g_M[(size_t)NV * NV];
// bf16 split copies of T: A = T*d (col k scaled by d[k]), B = T
__device__ __nv_bfloat16 g_Ah[(size_t)NV * NE];
__device__ __nv_bfloat16 g_Al[(size_t)NV * NE];
__device__ __nv_bfloat16 g_Bh[(size_t)NV * NE];
__device__ __nv_bfloat16 g_Bl[(size_t)NV * NE];
// bf16 split of A' = mask(M)*adj (row-major [i][k]) and HW^T ([n][k])
__device__ __nv_bfloat16 g_Aoh[(size_t)NV * NV];
__device__ __nv_bfloat16 g_Aol[(size_t)NV * NV];
__device__ __nv_bfloat16 g_HWh[FOUT * NV];
__device__ __nv_bfloat16 g_HWl[FOUT * NV];

// ======================= helpers =======================
__device__ __forceinline__ uint32_t smem_u32(const void* p) {
    uint32_t a;
    asm("{ .reg .u64 t; cvta.to.shared.u64 t, %1; cvt.u32.u64 %0, t; }" : "=r"(a) : "l"(p));
    return a;
}
__device__ __forceinline__ void split2(float x, float y, uint32_t& hi, uint32_t& lo) {
    __nv_bfloat162 h = __floats2bfloat162_rn(x, y);
    uint32_t hb = *(uint32_t*)&h;
    float hx = __uint_as_float(hb << 16);
    float hy = __uint_as_float(hb & 0xFFFF0000u);
    __nv_bfloat162 l = __floats2bfloat162_rn(x - hx, y - hy);
    hi = hb;
    lo = *(uint32_t*)&l;
}
__device__ __forceinline__ void mma16816(float* c, const uint32_t* a, const uint32_t* b) {
    asm volatile(
        "mma.sync.aligned.m16n8k16.row.col.f32.bf16.bf16.f32 "
        "{%0,%1,%2,%3}, {%4,%5,%6,%7}, {%8,%9}, {%0,%1,%2,%3};"
        : "+f"(c[0]), "+f"(c[1]), "+f"(c[2]), "+f"(c[3])
        : "r"(a[0]), "r"(a[1]), "r"(a[2]), "r"(a[3]), "r"(b[0]), "r"(b[1]));
}
__device__ __forceinline__ void ldsm_x4(uint32_t* r, uint32_t addr) {
    asm volatile("ldmatrix.sync.aligned.m8n8.x4.shared.b16 {%0,%1,%2,%3}, [%4];"
                 : "=r"(r[0]), "=r"(r[1]), "=r"(r[2]), "=r"(r[3]) : "r"(addr));
}
__device__ __forceinline__ void cp16cg(uint32_t saddr, const void* gaddr) {
    asm volatile("cp.async.cg.shared.global [%0], [%1], 16;" :: "r"(saddr), "l"(gaddr));
}

// ---------------- kernel 1: d[e] = dot(H_e[e,:], p) ----------------
__global__ void k_edge_dot(const float* __restrict__ He, const float* __restrict__ p) {
    int row  = blockIdx.x * 8 + (threadIdx.x >> 5);
    int lane = threadIdx.x & 31;
    const float* r = He + (size_t)row * FE;
    float s = r[lane] * p[lane] + r[lane + 32] * p[lane + 32];
    #pragma unroll
    for (int o = 16; o; o >>= 1) s += __shfl_xor_sync(0xffffffffu, s, o);
    if (lane == 0) g_d[row] = s;
}

// ---------------- kernel 1b: bf16 split precompute (T) ----------------
__global__ void __launch_bounds__(256) k_split(const float* __restrict__ T) {
    size_t idx = (size_t)blockIdx.x * 256 + threadIdx.x;
    int row = (int)(idx >> 10);
    int c0  = (int)(idx & 1023) * 8;
    const float* pt = T + (size_t)row * NE + c0;
    float4 t0 = *(const float4*)pt;
    float4 t1 = *(const float4*)(pt + 4);
    float4 d0 = *(const float4*)(g_d + c0);
    float4 d1 = *(const float4*)(g_d + c0 + 4);

    uint4 bh, bl, ah, al;
    split2(t0.x, t0.y, bh.x, bl.x);
    split2(t0.z, t0.w, bh.y, bl.y);
    split2(t1.x, t1.y, bh.z, bl.z);
    split2(t1.z, t1.w, bh.w, bl.w);
    split2(t0.x * d0.x, t0.y * d0.y, ah.x, al.x);
    split2(t0.z * d0.z, t0.w * d0.w, ah.y, al.y);
    split2(t1.x * d1.x, t1.y * d1.y, ah.z, al.z);
    split2(t1.z * d1.z, t1.w * d1.w, ah.w, al.w);

    size_t boff = ((size_t)row * NE + c0) * 2;
    *(uint4*)((char*)g_Ah + boff) = ah;
    *(uint4*)((char*)g_Al + boff) = al;
    *(uint4*)((char*)g_Bh + boff) = bh;
    *(uint4*)((char*)g_Bl + boff) = bl;
}

// ---------------- kernel 2: HW = H_v @ W, stored transposed bf16 split -----
// thread c holds HW[r0..r0+15][c] -> writes g_HWh/l[c][r0..r0+15] (k-contig).
__global__ void k_hw(const float* __restrict__ Hv, const float* __restrict__ W) {
    __shared__ float sh[16][FV];
    int r0  = blockIdx.x * 16;
    int tid = threadIdx.x;
    #pragma unroll
    for (int l = 0; l < 4; l++) {
        int idx = tid + l * 128;
        int r = idx >> 5;
        int c = (idx & 31) * 4;
        *(float4*)&sh[r][c] = *(const float4*)&Hv[(size_t)(r0 + r) * FV + c];
    }
    __syncthreads();
    int c = tid;
    float acc[16];
    #pragma unroll
    for (int r = 0; r < 16; r++) acc[r] = 0.f;
    for (int k = 0; k < FV; k++) {
        float w = W[k * FOUT + c];
        #pragma unroll
        for (int r = 0; r < 16; r++) acc[r] += sh[r][k] * w;
    }
    #pragma unroll
    for (int r = 0; r < 16; r += 2) {
        uint32_t hi, lo;
        split2(acc[r], acc[r + 1], hi, lo);
        size_t off = ((size_t)c * NV + r0 + r) * 2;
        *(uint32_t*)((char*)g_HWh + off) = hi;
        *(uint32_t*)((char*)g_HWl + off) = lo;
    }
}

// ---------------- kernel 3: M = (T*d) @ T^T via mma.sync bf16x3 ------------
// R14 build (proven 955us): unrolled x3, compile-time stage indices.
#define STG_B 16384
#define A_AH 0
#define A_AL 4096
#define A_BH 8192
#define A_BL 12288

__global__ void __launch_bounds__(256, 2) k_mult_hmma() {
    int idx = blockIdx.x;
    int bi = (int)((sqrtf(8.0f * (float)idx + 1.0f) - 1.0f) * 0.5f);
    while ((bi + 1) * (bi + 2) / 2 <= idx) bi++;
    while (bi * (bi + 1) / 2 > idx) bi--;
    int bj = idx - bi * (bi + 1) / 2;

    __shared__ __align__(128) char smem[3 * STG_B];
    const uint32_t sb = smem_u32(smem);

    const int tid = threadIdx.x, lane = tid & 31, wid = tid >> 5;
    const int wr = wid >> 2, wc = wid & 3;

    float acc[4][4][4];
    #pragma unroll
    for (int i = 0; i < 4; i++)
        #pragma unroll
        for (int j = 0; j < 4; j++)
            #pragma unroll
            for (int q = 0; q < 4; q++) acc[i][j][q] = 0.f;

    const int crow = tid >> 1;
    const int cc   = tid & 1;
    const uint32_t cdst = (uint32_t)(crow * 32 + ((cc ^ ((crow >> 2) & 1)) * 16));
    const __nv_bfloat16* gAh_t = g_Ah + (size_t)(bi * 128 + crow) * NE + cc * 8;
    const __nv_bfloat16* gAl_t = g_Al + (size_t)(bi * 128 + crow) * NE + cc * 8;
    const __nv_bfloat16* gBh_t = g_Bh + (size_t)(bj * 128 + crow) * NE + cc * 8;
    const __nv_bfloat16* gBl_t = g_Bl + (size_t)(bj * 128 + crow) * NE + cc * 8;

    #define ISSUE(stage, k0)                                   \
        do {                                                   \
            uint32_t st_ = sb + (stage) * STG_B;               \
            cp16cg(st_ + A_AH + cdst, gAh_t + (k0));           \
            cp16cg(st_ + A_AL + cdst, gAl_t + (k0));           \
            cp16cg(st_ + A_BH + cdst, gBh_t + (k0));           \
            cp16cg(st_ + A_BL + cdst, gBl_t + (k0));           \
        } while (0)

    const int arow_l = wr * 64 + (lane & 15);
    const int ac     = lane >> 4;
    const int bm     = lane >> 3;
    const int brow_l = wc * 32 + (bm >> 1) * 8 + (lane & 7);
    const int bc     = bm & 1;

    uint32_t offB[2], offA[4];
    #pragma unroll
    for (int np = 0; np < 2; np++) {
        int row = brow_l + np * 16;
        offB[np] = (uint32_t)(row * 32 + ((bc ^ ((row >> 2) & 1)) * 16));
    }
    #pragma unroll
    for (int mt = 0; mt < 4; mt++) {
        int row = arow_l + mt * 16;
        offA[mt] = (uint32_t)(row * 32 + ((ac ^ ((row >> 2) & 1)) * 16));
    }

    #define CHUNK(CSTG, ISTG)                                                  \
        do {                                                                   \
            asm volatile("cp.async.wait_group 1;" ::: "memory");               \
            __syncthreads();                                                   \
            const uint32_t st = sb + (CSTG) * STG_B;                           \
            uint32_t bh[2][4], bl[2][4];                                       \
            _Pragma("unroll")                                                  \
            for (int np = 0; np < 2; np++) {                                   \
                ldsm_x4(bh[np], st + A_BH + offB[np]);                         \
                ldsm_x4(bl[np], st + A_BL + offB[np]);                         \
            }                                                                  \
            _Pragma("unroll")                                                  \
            for (int mt = 0; mt < 4; mt++) {                                   \
                uint32_t ah[4], al[4];                                         \
                ldsm_x4(ah, st + A_AH + offA[mt]);                             \
                ldsm_x4(al, st + A_AL + offA[mt]);                             \
                _Pragma("unroll")                                              \
                for (int nt = 0; nt < 4; nt++) {                               \
                    const uint32_t* pbh = &bh[nt >> 1][(nt & 1) * 2];          \
                    const uint32_t* pbl = &bl[nt >> 1][(nt & 1) * 2];          \
                    mma16816(acc[mt][nt], ah, pbh);                            \
                    mma16816(acc[mt][nt], ah, pbl);                            \
                    mma16816(acc[mt][nt], al, pbh);                            \
                }                                                              \
            }                                                                  \
            if (k_next < NE) ISSUE(ISTG, k_next);                              \
            asm volatile("cp.async.commit_group;");                            \
            k_next += 16;                                                      \
        } while (0)

    ISSUE(0, 0);
    asm volatile("cp.async.commit_group;");
    ISSUE(1, 16);
    asm volatile("cp.async.commit_group;");

    int k_next = 32;
    #pragma unroll 1
    for (int s3 = 0; s3 < 170; s3++) {
        CHUNK(0, 2);
        CHUNK(1, 0);
        CHUNK(2, 1);
    }
    CHUNK(0, 2);
    CHUNK(1, 0);

    const int g  = lane >> 2;
    const int cp = (lane & 3) * 2;
    #pragma unroll
    for (int mt = 0; mt < 4; mt++)
        #pragma unroll
        for (int nt = 0; nt < 4; nt++) {
            float* c = acc[mt][nt];
            int r = bi * 128 + wr * 64 + mt * 16 + g;
            int q = bj * 128 + wc * 32 + nt * 8 + cp;
            *(float2*)&g_M[(size_t)r * NV + q]       = make_float2(c[0], c[1]);
            *(float2*)&g_M[(size_t)(r + 8) * NV + q] = make_float2(c[2], c[3]);
            if (bi != bj) {
                g_M[(size_t)q * NV + r]           = c[0];
                g_M[(size_t)(q + 1) * NV + r]     = c[1];
                g_M[(size_t)q * NV + r + 8]       = c[2];
                g_M[(size_t)(q + 1) * NV + r + 8] = c[3];
            }
        }
}

// ---------------- kernel 3b: A' = (diag ? adj : adj*M) -> bf16 hi/lo -------
__global__ void __launch_bounds__(256) k_osplit(const float* __restrict__ adj_v) {
    size_t idx = (size_t)blockIdx.x * 256 + threadIdx.x;
    int row = (int)(idx >> 9);          // 512 slots of 8 per row
    int c0  = (int)(idx & 511) * 8;
    size_t base = (size_t)row * NV + c0;
    float4 a0 = *(const float4*)(adj_v + base);
    float4 a1 = *(const float4*)(adj_v + base + 4);
    float4 m0 = *(const float4*)(g_M + base);
    float4 m1 = *(const float4*)(g_M + base + 4);

    float v[8];
    v[0] = a0.x * m0.x; v[1] = a0.y * m0.y; v[2] = a0.z * m0.z; v[3] = a0.w * m0.w;
    v[4] = a1.x * m1.x; v[5] = a1.y * m1.y; v[6] = a1.z * m1.z; v[7] = a1.w * m1.w;
    float av[8] = {a0.x, a0.y, a0.z, a0.w, a1.x, a1.y, a1.z, a1.w};
    int dj = row - c0;                  // diag index within [0,8) if present
    if (dj >= 0 && dj < 8) v[dj] = av[dj];

    uint4 hi, lo;
    split2(v[0], v[1], hi.x, lo.x);
    split2(v[2], v[3], hi.y, lo.y);
    split2(v[4], v[5], hi.z, lo.z);
    split2(v[6], v[7], hi.w, lo.w);
    size_t boff = base * 2;
    *(uint4*)((char*)g_Aoh + boff) = hi;
    *(uint4*)((char*)g_Aol + boff) = lo;
}

// ---------------- kernel 4: out = A' @ HW^T + bias via mma.sync bf16x3 -----
// 128 CTAs x (32 rows x 128 cols), K=4096, same pipeline skeleton as k_mult.
// stage (10KB): A'h | A'l (32 rows x 32B) | Bh | Bl (128 rows x 32B)
#define O_AH 0
#define O_AL 1024
#define O_BH 2048
#define O_BL 6144
#define O_STG 10240

__global__ void __launch_bounds__(256) k_out_hmma(const float* __restrict__ bias,
                                                  float* __restrict__ out) {
    const int bi  = blockIdx.x;         // 32-row band
    __shared__ __align__(128) char smem[3 * O_STG];
    const uint32_t sb = smem_u32(smem);

    const int tid = threadIdx.x, lane = tid & 31, wid = tid >> 5;
    const int wm = wid >> 2, wn = wid & 3;   // warp: m16 band (of 2), n32 band (of 4)

    float acc[4][4];
    #pragma unroll
    for (int j = 0; j < 4; j++)
        #pragma unroll
        for (int q = 0; q < 4; q++) acc[j][q] = 0.f;

    // cp.async mapping: B: all 256 threads (128 rows x 2 c16); A: threads 0-63.
    const int brow_c = tid >> 1;
    const int bcc    = tid & 1;
    const uint32_t bdst = (uint32_t)(brow_c * 32 + ((bcc ^ ((brow_c >> 2) & 1)) * 16));
    const __nv_bfloat16* gBh_t = g_HWh + (size_t)brow_c * NV + bcc * 8;
    const __nv_bfloat16* gBl_t = g_HWl + (size_t)brow_c * NV + bcc * 8;
    const int acrow = (tid & 63) >> 1;
    const int accc  = tid & 1;
    const uint32_t adst = (uint32_t)(acrow * 32 + ((accc ^ ((acrow >> 2) & 1)) * 16));
    const __nv_bfloat16* gAh_t = g_Aoh + (size_t)(bi * 32 + acrow) * NV + accc * 8;
    const __nv_bfloat16* gAl_t = g_Aol + (size_t)(bi * 32 + acrow) * NV + accc * 8;
    const bool doA = (tid < 64);

    #define ISSUE_O(stage, k0)                                  \
        do {                                                    \
            uint32_t st_ = sb + (stage) * O_STG;                \
            if (doA) {                                          \
                cp16cg(st_ + O_AH + adst, gAh_t + (k0));        \
                cp16cg(st_ + O_AL + adst, gAl_t + (k0));        \
            }                                                   \
            cp16cg(st_ + O_BH + bdst, gBh_t + (k0));            \
            cp16cg(st_ + O_BL + bdst, gBl_t + (k0));            \
        } while (0)

    // ldsm lane bases
    const int arow_l = wm * 16 + (lane & 15);
    const int ac     = lane >> 4;
    const uint32_t offA = (uint32_t)(arow_l * 32 + ((ac ^ ((arow_l >> 2) & 1)) * 16));
    const int bm     = lane >> 3;
    const int brow_l = wn * 32 + (bm >> 1) * 8 + (lane & 7);
    const int bc     = bm & 1;
    uint32_t offB[2];
    #pragma unroll
    for (int np = 0; np < 2; np++) {
        int row = brow_l + np * 16;
        offB[np] = (uint32_t)(row * 32 + ((bc ^ ((row >> 2) & 1)) * 16));
    }

    #define CHUNK_O(CSTG, ISTG)                                                \
        do {                                                                   \
            asm volatile("cp.async.wait_group 1;" ::: "memory");               \
            __syncthreads();                                                   \
            const uint32_t st = sb + (CSTG) * O_STG;                           \
            uint32_t bh[2][4], bl[2][4];                                       \
            _Pragma("unroll")                                                  \
            for (int np = 0; np < 2; np++) {                                   \
                ldsm_x4(bh[np], st + O_BH + offB[np]);                         \
                ldsm_x4(bl[np], st + O_BL + offB[np]);                         \
            }                                                                  \
            {                                                                  \
                uint32_t ah[4], al[4];                                         \
                ldsm_x4(ah, st + O_AH + offA);                                 \
                ldsm_x4(al, st + O_AL + offA);                                 \
                _Pragma("unroll")                                              \
                for (int nt = 0; nt < 4; nt++) {                               \
                    const uint32_t* pbh = &bh[nt >> 1][(nt & 1) * 2];          \
                    const uint32_t* pbl = &bl[nt >> 1][(nt & 1) * 2];          \
                    mma16816(acc[nt], ah, pbh);                                \
                    mma16816(acc[nt], ah, pbl);                                \
                    mma16816(acc[nt], al, pbh);                                \
                }                                                              \
            }                                                                  \
            if (k_next < NV) ISSUE_O(ISTG, k_next);                            \
            asm volatile("cp.async.commit_group;");                            \
            k_next += 16;                                                      \
        } while (0)

    ISSUE_O(0, 0);
    asm volatile("cp.async.commit_group;");
    ISSUE_O(1, 16);
    asm volatile("cp.async.commit_group;");

    int k_next = 32;
    // 256 chunks = 85*3 + 1
    #pragma unroll 1
    for (int s3 = 0; s3 < 85; s3++) {
        CHUNK_O(0, 2);
        CHUNK_O(1, 0);
        CHUNK_O(2, 1);
    }
    CHUNK_O(0, 2);

    // epilogue: bias add + store
    const int g  = lane >> 2;
    const int cp = (lane & 3) * 2;
    const int r0g = bi * 32 + wm * 16 + g;
    #pragma unroll
    for (int nt = 0; nt < 4; nt++) {
        int col = wn * 32 + nt * 8 + cp;
        float2 bv = *(const float2*)&bias[col];
        *(float2*)&out[(size_t)r0g * FOUT + col] =
            make_float2(acc[nt][0] + bv.x, acc[nt][1] + bv.y);
        *(float2*)&out[(size_t)(r0g + 8) * FOUT + col] =
            make_float2(acc[nt][2] + bv.x, acc[nt][3] + bv.y);
    }
}

// ---------------- launch ----------------
extern "C" void kernel_launch(void* const* d_in, const int* in_sizes, int n_in,
                              void* d_out, int out_size) {
    const float* Hv    = (const float*)d_in[0];
    const float* He    = (const float*)d_in[1];
    // d_in[2] = adj_e: unused by the node_layer path
    const float* adj_v = (const float*)d_in[3];
    const float* T     = (const float*)d_in[4];
    const float* W     = (const float*)d_in[5];
    const float* p     = (const float*)d_in[6];
    const float* bias  = (const float*)d_in[7];
    float* out = (float*)d_out;

    k_edge_dot<<<NE / 8, 256>>>(He, p);
    k_split<<<(NV * (NE / 8)) / 256, 256>>>(T);
    k_hw<<<NV / 16, 128>>>(Hv, W);
    k_mult_hmma<<<528, 256>>>();
    k_osplit<<<(NV * (NV / 8)) / 256, 256>>>(adj_v);
    k_out_hmma<<<NV / 32, 256>>>(bias, out);

    // second output of the tuple: H_e passthrough
    if (out_size >= NV * FOUT + NE * FE) {
        cudaMemcpyAsync(out + NV * FOUT, He, (size_t)NE * FE * sizeof(float),
                        cudaMemcpyDeviceToDevice);
    }
}

// round 16
// speedup vs baseline: 1.2417x; 1.0024x over previous
#include <cuda_runtime.h>
#include <cuda_bf16.h>
#include <cstdint>

#define NV 4096
#define NE 8192
#define FV 128
#define FE 64
#define FOUT 128

// Scratch (allocation-free rule: __device__ globals)
__device__ float g_d[NE];
// bf16 split copies of T: A = T*d (col k scaled by d[k]), B = T
__device__ __nv_bfloat16 g_Ah[(size_t)NV * NE];
__device__ __nv_bfloat16 g_Al[(size_t)NV * NE];
__device__ __nv_bfloat16 g_Bh[(size_t)NV * NE];
__device__ __nv_bfloat16 g_Bl[(size_t)NV * NE];
// bf16 split of A' = mask(M)*adj (row-major [i][k]) and HW^T ([n][k])
__device__ __nv_bfloat16 g_Aoh[(size_t)NV * NV];
__device__ __nv_bfloat16 g_Aol[(size_t)NV * NV];
__device__ __nv_bfloat16 g_HWh[FOUT * NV];
__device__ __nv_bfloat16 g_HWl[FOUT * NV];

// ======================= helpers =======================
__device__ __forceinline__ uint32_t smem_u32(const void* p) {
    uint32_t a;
    asm("{ .reg .u64 t; cvta.to.shared.u64 t, %1; cvt.u32.u64 %0, t; }" : "=r"(a) : "l"(p));
    return a;
}
__device__ __forceinline__ void split2(float x, float y, uint32_t& hi, uint32_t& lo) {
    __nv_bfloat162 h = __floats2bfloat162_rn(x, y);
    uint32_t hb = *(uint32_t*)&h;
    float hx = __uint_as_float(hb << 16);
    float hy = __uint_as_float(hb & 0xFFFF0000u);
    __nv_bfloat162 l = __floats2bfloat162_rn(x - hx, y - hy);
    hi = hb;
    lo = *(uint32_t*)&l;
}
__device__ __forceinline__ void split1(float x, __nv_bfloat16& hi, __nv_bfloat16& lo) {
    hi = __float2bfloat16_rn(x);
    lo = __float2bfloat16_rn(x - __bfloat162float(hi));
}
__device__ __forceinline__ void mma16816(float* c, const uint32_t* a, const uint32_t* b) {
    asm volatile(
        "mma.sync.aligned.m16n8k16.row.col.f32.bf16.bf16.f32 "
        "{%0,%1,%2,%3}, {%4,%5,%6,%7}, {%8,%9}, {%0,%1,%2,%3};"
        : "+f"(c[0]), "+f"(c[1]), "+f"(c[2]), "+f"(c[3])
        : "r"(a[0]), "r"(a[1]), "r"(a[2]), "r"(a[3]), "r"(b[0]), "r"(b[1]));
}
__device__ __forceinline__ void ldsm_x4(uint32_t* r, uint32_t addr) {
    asm volatile("ldmatrix.sync.aligned.m8n8.x4.shared.b16 {%0,%1,%2,%3}, [%4];"
                 : "=r"(r[0]), "=r"(r[1]), "=r"(r[2]), "=r"(r[3]) : "r"(addr));
}
__device__ __forceinline__ void cp16cg(uint32_t saddr, const void* gaddr) {
    asm volatile("cp.async.cg.shared.global [%0], [%1], 16;" :: "r"(saddr), "l"(gaddr));
}

// ---------------- kernel 1: d[e] = dot(H_e[e,:], p) ----------------
__global__ void k_edge_dot(const float* __restrict__ He, const float* __restrict__ p) {
    int row  = blockIdx.x * 8 + (threadIdx.x >> 5);
    int lane = threadIdx.x & 31;
    const float* r = He + (size_t)row * FE;
    float s = r[lane] * p[lane] + r[lane + 32] * p[lane + 32];
    #pragma unroll
    for (int o = 16; o; o >>= 1) s += __shfl_xor_sync(0xffffffffu, s, o);
    if (lane == 0) g_d[row] = s;
}

// ---------------- kernel 1b: bf16 split precompute (T) ----------------
__global__ void __launch_bounds__(256) k_split(const float* __restrict__ T) {
    size_t idx = (size_t)blockIdx.x * 256 + threadIdx.x;
    int row = (int)(idx >> 10);
    int c0  = (int)(idx & 1023) * 8;
    const float* pt = T + (size_t)row * NE + c0;
    float4 t0 = *(const float4*)pt;
    float4 t1 = *(const float4*)(pt + 4);
    float4 d0 = *(const float4*)(g_d + c0);
    float4 d1 = *(const float4*)(g_d + c0 + 4);

    uint4 bh, bl, ah, al;
    split2(t0.x, t0.y, bh.x, bl.x);
    split2(t0.z, t0.w, bh.y, bl.y);
    split2(t1.x, t1.y, bh.z, bl.z);
    split2(t1.z, t1.w, bh.w, bl.w);
    split2(t0.x * d0.x, t0.y * d0.y, ah.x, al.x);
    split2(t0.z * d0.z, t0.w * d0.w, ah.y, al.y);
    split2(t1.x * d1.x, t1.y * d1.y, ah.z, al.z);
    split2(t1.z * d1.z, t1.w * d1.w, ah.w, al.w);

    size_t boff = ((size_t)row * NE + c0) * 2;
    *(uint4*)((char*)g_Ah + boff) = ah;
    *(uint4*)((char*)g_Al + boff) = al;
    *(uint4*)((char*)g_Bh + boff) = bh;
    *(uint4*)((char*)g_Bl + boff) = bl;
}

// ---------------- kernel 2: HW = H_v @ W, stored transposed bf16 split -----
__global__ void k_hw(const float* __restrict__ Hv, const float* __restrict__ W) {
    __shared__ float sh[16][FV];
    int r0  = blockIdx.x * 16;
    int tid = threadIdx.x;
    #pragma unroll
    for (int l = 0; l < 4; l++) {
        int idx = tid + l * 128;
        int r = idx >> 5;
        int c = (idx & 31) * 4;
        *(float4*)&sh[r][c] = *(const float4*)&Hv[(size_t)(r0 + r) * FV + c];
    }
    __syncthreads();
    int c = tid;
    float acc[16];
    #pragma unroll
    for (int r = 0; r < 16; r++) acc[r] = 0.f;
    for (int k = 0; k < FV; k++) {
        float w = W[k * FOUT + c];
        #pragma unroll
        for (int r = 0; r < 16; r++) acc[r] += sh[r][k] * w;
    }
    #pragma unroll
    for (int r = 0; r < 16; r += 2) {
        uint32_t hi, lo;
        split2(acc[r], acc[r + 1], hi, lo);
        size_t off = ((size_t)c * NV + r0 + r) * 2;
        *(uint32_t*)((char*)g_HWh + off) = hi;
        *(uint32_t*)((char*)g_HWl + off) = lo;
    }
}

// ---------------- kernel 3: M = (T*d) @ T^T via mma.sync bf16x3 ------------
// R14 mainloop (proven 955us, frozen). Epilogue fused with osplit: applies
// adj mask/product to the register-resident M tile and stores the bf16 split
// of A' = (diag ? adj : adj*M) directly — g_M never touches memory.
#define STG_B 16384
#define A_AH 0
#define A_AL 4096
#define A_BH 8192
#define A_BL 12288

__global__ void __launch_bounds__(256, 2) k_mult_hmma(const float* __restrict__ adj_v) {
    int idx = blockIdx.x;
    int bi = (int)((sqrtf(8.0f * (float)idx + 1.0f) - 1.0f) * 0.5f);
    while ((bi + 1) * (bi + 2) / 2 <= idx) bi++;
    while (bi * (bi + 1) / 2 > idx) bi--;
    int bj = idx - bi * (bi + 1) / 2;

    __shared__ __align__(128) char smem[3 * STG_B];
    const uint32_t sb = smem_u32(smem);

    const int tid = threadIdx.x, lane = tid & 31, wid = tid >> 5;
    const int wr = wid >> 2, wc = wid & 3;

    float acc[4][4][4];
    #pragma unroll
    for (int i = 0; i < 4; i++)
        #pragma unroll
        for (int j = 0; j < 4; j++)
            #pragma unroll
            for (int q = 0; q < 4; q++) acc[i][j][q] = 0.f;

    const int crow = tid >> 1;
    const int cc   = tid & 1;
    const uint32_t cdst = (uint32_t)(crow * 32 + ((cc ^ ((crow >> 2) & 1)) * 16));
    const __nv_bfloat16* gAh_t = g_Ah + (size_t)(bi * 128 + crow) * NE + cc * 8;
    const __nv_bfloat16* gAl_t = g_Al + (size_t)(bi * 128 + crow) * NE + cc * 8;
    const __nv_bfloat16* gBh_t = g_Bh + (size_t)(bj * 128 + crow) * NE + cc * 8;
    const __nv_bfloat16* gBl_t = g_Bl + (size_t)(bj * 128 + crow) * NE + cc * 8;

    #define ISSUE(stage, k0)                                   \
        do {                                                   \
            uint32_t st_ = sb + (stage) * STG_B;               \
            cp16cg(st_ + A_AH + cdst, gAh_t + (k0));           \
            cp16cg(st_ + A_AL + cdst, gAl_t + (k0));           \
            cp16cg(st_ + A_BH + cdst, gBh_t + (k0));           \
            cp16cg(st_ + A_BL + cdst, gBl_t + (k0));           \
        } while (0)

    const int arow_l = wr * 64 + (lane & 15);
    const int ac     = lane >> 4;
    const int bm     = lane >> 3;
    const int brow_l = wc * 32 + (bm >> 1) * 8 + (lane & 7);
    const int bc     = bm & 1;

    uint32_t offB[2], offA[4];
    #pragma unroll
    for (int np = 0; np < 2; np++) {
        int row = brow_l + np * 16;
        offB[np] = (uint32_t)(row * 32 + ((bc ^ ((row >> 2) & 1)) * 16));
    }
    #pragma unroll
    for (int mt = 0; mt < 4; mt++) {
        int row = arow_l + mt * 16;
        offA[mt] = (uint32_t)(row * 32 + ((ac ^ ((row >> 2) & 1)) * 16));
    }

    #define CHUNK(CSTG, ISTG)                                                  \
        do {                                                                   \
            asm volatile("cp.async.wait_group 1;" ::: "memory");               \
            __syncthreads();                                                   \
            const uint32_t st = sb + (CSTG) * STG_B;                           \
            uint32_t bh[2][4], bl[2][4];                                       \
            _Pragma("unroll")                                                  \
            for (int np = 0; np < 2; np++) {                                   \
                ldsm_x4(bh[np], st + A_BH + offB[np]);                         \
                ldsm_x4(bl[np], st + A_BL + offB[np]);                         \
            }                                                                  \
            _Pragma("unroll")                                                  \
            for (int mt = 0; mt < 4; mt++) {                                   \
                uint32_t ah[4], al[4];                                         \
                ldsm_x4(ah, st + A_AH + offA[mt]);                             \
                ldsm_x4(al, st + A_AL + offA[mt]);                             \
                _Pragma("unroll")                                              \
                for (int nt = 0; nt < 4; nt++) {                               \
                    const uint32_t* pbh = &bh[nt >> 1][(nt & 1) * 2];          \
                    const uint32_t* pbl = &bl[nt >> 1][(nt & 1) * 2];          \
                    mma16816(acc[mt][nt], ah, pbh);                            \
                    mma16816(acc[mt][nt], ah, pbl);                            \
                    mma16816(acc[mt][nt], al, pbh);                            \
                }                                                              \
            }                                                                  \
            if (k_next < NE) ISSUE(ISTG, k_next);                              \
            asm volatile("cp.async.commit_group;");                            \
            k_next += 16;                                                      \
        } while (0)

    ISSUE(0, 0);
    asm volatile("cp.async.commit_group;");
    ISSUE(1, 16);
    asm volatile("cp.async.commit_group;");

    int k_next = 32;
    #pragma unroll 1
    for (int s3 = 0; s3 < 170; s3++) {
        CHUNK(0, 2);
        CHUNK(1, 0);
        CHUNK(2, 1);
    }
    CHUNK(0, 2);
    CHUNK(1, 0);

    // ---- fused epilogue: A' = (diag ? adj : adj*M), bf16 split ----
    const int g  = lane >> 2;
    const int cp = (lane & 3) * 2;
    #pragma unroll
    for (int mt = 0; mt < 4; mt++)
        #pragma unroll
        for (int nt = 0; nt < 4; nt++) {
            float* c = acc[mt][nt];
            int r = bi * 128 + wr * 64 + mt * 16 + g;
            int q = bj * 128 + wc * 32 + nt * 8 + cp;

            // primary tile rows r, r+8, cols q, q+1 (coalesced 4B stores)
            float2 a0 = *(const float2*)(adj_v + (size_t)r * NV + q);
            float2 a1 = *(const float2*)(adj_v + (size_t)(r + 8) * NV + q);
            float v00 = (r == q)         ? a0.x : a0.x * c[0];
            float v01 = (r == q + 1)     ? a0.y : a0.y * c[1];
            float v10 = (r + 8 == q)     ? a1.x : a1.x * c[2];
            float v11 = (r + 8 == q + 1) ? a1.y : a1.y * c[3];
            uint32_t h0, l0, h1, l1;
            split2(v00, v01, h0, l0);
            split2(v10, v11, h1, l1);
            size_t o0 = ((size_t)r * NV + q) * 2;
            size_t o1 = ((size_t)(r + 8) * NV + q) * 2;
            *(uint32_t*)((char*)g_Aoh + o0) = h0;
            *(uint32_t*)((char*)g_Aol + o0) = l0;
            *(uint32_t*)((char*)g_Aoh + o1) = h1;
            *(uint32_t*)((char*)g_Aol + o1) = l1;

            // mirror tile (bi != bj -> r != q always): scalar bf16 stores
            if (bi != bj) {
                float m00 = adj_v[(size_t)q * NV + r] * c[0];
                float m01 = adj_v[(size_t)(q + 1) * NV + r] * c[1];
                float m10 = adj_v[(size_t)q * NV + r + 8] * c[2];
                float m11 = adj_v[(size_t)(q + 1) * NV + r + 8] * c[3];
                __nv_bfloat16 hh, ll;
                split1(m00, hh, ll);
                g_Aoh[(size_t)q * NV + r] = hh;       g_Aol[(size_t)q * NV + r] = ll;
                split1(m01, hh, ll);
                g_Aoh[(size_t)(q + 1) * NV + r] = hh; g_Aol[(size_t)(q + 1) * NV + r] = ll;
                split1(m10, hh, ll);
                g_Aoh[(size_t)q * NV + r + 8] = hh;   g_Aol[(size_t)q * NV + r + 8] = ll;
                split1(m11, hh, ll);
                g_Aoh[(size_t)(q + 1) * NV + r + 8] = hh;
                g_Aol[(size_t)(q + 1) * NV + r + 8] = ll;
            }
        }
}

// ---------------- kernel 4: out = A' @ HW^T + bias via mma.sync bf16x3 -----
// 128 CTAs x (32 rows x 128 cols), K=4096 (R15 build, frozen).
#define O_AH 0
#define O_AL 1024
#define O_BH 2048
#define O_BL 6144
#define O_STG 10240

__global__ void __launch_bounds__(256) k_out_hmma(const float* __restrict__ bias,
                                                  float* __restrict__ out) {
    const int bi  = blockIdx.x;
    __shared__ __align__(128) char smem[3 * O_STG];
    const uint32_t sb = smem_u32(smem);

    const int tid = threadIdx.x, lane = tid & 31, wid = tid >> 5;
    const int wm = wid >> 2, wn = wid & 3;

    float acc[4][4];
    #pragma unroll
    for (int j = 0; j < 4; j++)
        #pragma unroll
        for (int q = 0; q < 4; q++) acc[j][q] = 0.f;

    const int brow_c = tid >> 1;
    const int bcc    = tid & 1;
    const uint32_t bdst = (uint32_t)(brow_c * 32 + ((bcc ^ ((brow_c >> 2) & 1)) * 16));
    const __nv_bfloat16* gBh_t = g_HWh + (size_t)brow_c * NV + bcc * 8;
    const __nv_bfloat16* gBl_t = g_HWl + (size_t)brow_c * NV + bcc * 8;
    const int acrow = (tid & 63) >> 1;
    const int accc  = tid & 1;
    const uint32_t adst = (uint32_t)(acrow * 32 + ((accc ^ ((acrow >> 2) & 1)) * 16));
    const __nv_bfloat16* gAh_t = g_Aoh + (size_t)(bi * 32 + acrow) * NV + accc * 8;
    const __nv_bfloat16* gAl_t = g_Aol + (size_t)(bi * 32 + acrow) * NV + accc * 8;
    const bool doA = (tid < 64);

    #define ISSUE_O(stage, k0)                                  \
        do {                                                    \
            uint32_t st_ = sb + (stage) * O_STG;                \
            if (doA) {                                          \
                cp16cg(st_ + O_AH + adst, gAh_t + (k0));        \
                cp16cg(st_ + O_AL + adst, gAl_t + (k0));        \
            }                                                   \
            cp16cg(st_ + O_BH + bdst, gBh_t + (k0));            \
            cp16cg(st_ + O_BL + bdst, gBl_t + (k0));            \
        } while (0)

    const int arow_l = wm * 16 + (lane & 15);
    const int ac     = lane >> 4;
    const uint32_t offA = (uint32_t)(arow_l * 32 + ((ac ^ ((arow_l >> 2) & 1)) * 16));
    const int bm     = lane >> 3;
    const int brow_l = wn * 32 + (bm >> 1) * 8 + (lane & 7);
    const int bc     = bm & 1;
    uint32_t offB[2];
    #pragma unroll
    for (int np = 0; np < 2; np++) {
        int row = brow_l + np * 16;
        offB[np] = (uint32_t)(row * 32 + ((bc ^ ((row >> 2) & 1)) * 16));
    }

    #define CHUNK_O(CSTG, ISTG)                                                \
        do {                                                                   \
            asm volatile("cp.async.wait_group 1;" ::: "memory");               \
            __syncthreads();                                                   \
            const uint32_t st = sb + (CSTG) * O_STG;                           \
            uint32_t bh[2][4], bl[2][4];                                       \
            _Pragma("unroll")                                                  \
            for (int np = 0; np < 2; np++) {                                   \
                ldsm_x4(bh[np], st + O_BH + offB[np]);                         \
                ldsm_x4(bl[np], st + O_BL + offB[np]);                         \
            }                                                                  \
            {                                                                  \
                uint32_t ah[4], al[4];                                         \
                ldsm_x4(ah, st + O_AH + offA);                                 \
                ldsm_x4(al, st + O_AL + offA);                                 \
                _Pragma("unroll")                                              \
                for (int nt = 0; nt < 4; nt++) {                               \
                    const uint32_t* pbh = &bh[nt >> 1][(nt & 1) * 2];          \
                    const uint32_t* pbl = &bl[nt >> 1][(nt & 1) * 2];          \
                    mma16816(acc[nt], ah, pbh);                                \
                    mma16816(acc[nt], ah, pbl);                                \
                    mma16816(acc[nt], al, pbh);                                \
                }                                                              \
            }                                                                  \
            if (k_next < NV) ISSUE_O(ISTG, k_next);                            \
            asm volatile("cp.async.commit_group;");                            \
            k_next += 16;                                                      \
        } while (0)

    ISSUE_O(0, 0);
    asm volatile("cp.async.commit_group;");
    ISSUE_O(1, 16);
    asm volatile("cp.async.commit_group;");

    int k_next = 32;
    #pragma unroll 1
    for (int s3 = 0; s3 < 85; s3++) {
        CHUNK_O(0, 2);
        CHUNK_O(1, 0);
        CHUNK_O(2, 1);
    }
    CHUNK_O(0, 2);

    const int g  = lane >> 2;
    const int cp = (lane & 3) * 2;
    const int r0g = bi * 32 + wm * 16 + g;
    #pragma unroll
    for (int nt = 0; nt < 4; nt++) {
        int col = wn * 32 + nt * 8 + cp;
        float2 bv = *(const float2*)&bias[col];
        *(float2*)&out[(size_t)r0g * FOUT + col] =
            make_float2(acc[nt][0] + bv.x, acc[nt][1] + bv.y);
        *(float2*)&out[(size_t)(r0g + 8) * FOUT + col] =
            make_float2(acc[nt][2] + bv.x, acc[nt][3] + bv.y);
    }
}

// ---------------- launch ----------------
extern "C" void kernel_launch(void* const* d_in, const int* in_sizes, int n_in,
                              void* d_out, int out_size) {
    const float* Hv    = (const float*)d_in[0];
    const float* He    = (const float*)d_in[1];
    // d_in[2] = adj_e: unused by the node_layer path
    const float* adj_v = (const float*)d_in[3];
    const float* T     = (const float*)d_in[4];
    const float* W     = (const float*)d_in[5];
    const float* p     = (const float*)d_in[6];
    const float* bias  = (const float*)d_in[7];
    float* out = (float*)d_out;

    k_edge_dot<<<NE / 8, 256>>>(He, p);
    k_split<<<(NV * (NE / 8)) / 256, 256>>>(T);
    k_hw<<<NV / 16, 128>>>(Hv, W);
    k_mult_hmma<<<528, 256>>>(adj_v);
    k_out_hmma<<<NV / 32, 256>>>(bias, out);

    // second output of the tuple: H_e passthrough
    if (out_size >= NV * FOUT + NE * FE) {
        cudaMemcpyAsync(out + NV * FOUT, He, (size_t)NE * FE * sizeof(float),
                        cudaMemcpyDeviceToDevice);
    }
}